// round 14
// baseline (speedup 1.0000x reference)
#include <cuda_runtime.h>
#include <cuda_fp16.h>
#include <cstdint>

// Dims: B=32, L=1024, E=512, D=512. M = 32768 rows, N = 4096. K0=512, K1=1024.
#define SCALE_F 1.4142135623730951f

// ---------------------------------------------------------------------------
// Scratch (device globals)
// ---------------------------------------------------------------------------
__device__ __half g_Ah[33554432];   // fp16 A: layer0 seqs (32768x512), then h0 (32768x1024)
__device__ __half g_Wh[4194304];    // fp16 W [K, 4096], COLUMNS PERMUTED (gate-interleaved)
__device__ __half g_Uh[134217728];  // fp16 U (32768 x 4096), gate-interleaved columns

// ---------------------------------------------------------------------------
// Converters
// ---------------------------------------------------------------------------
__global__ void k_cvtA(const float4* __restrict__ s, int n4) {
    int i = blockIdx.x * blockDim.x + threadIdx.x;
    if (i < n4) {
        float4 v = s[i];
        __half2* dp = reinterpret_cast<__half2*>(g_Ah);
        dp[2 * i]     = __floats2half2_rn(v.x, v.y);
        dp[2 * i + 1] = __floats2half2_rn(v.z, v.w);
    }
}

// W [K,4096] fp32 -> g_Wh [K,4096] fp16, columns permuted so U's 4 gate values
// for (dir,d) are contiguous: new col (dir*512+d)*4+gate = old col dir*2048+gate*512+d.
__global__ void k_cvtWT(const float* __restrict__ W, int K) {
    int id = blockIdx.x * blockDim.x + threadIdx.x;   // K * 1024 ids
    int d   = id & 511;
    int dir = (id >> 9) & 1;
    int k   = id >> 10;
    if (k >= K) return;
    const float* src = W + (size_t)k * 4096 + dir * 2048 + d;
    float w0 = src[0], w1 = src[512], w2 = src[1024], w3 = src[1536];
    uint2 v;
    __half2 p0 = __floats2half2_rn(w0, w1);
    __half2 p1 = __floats2half2_rn(w2, w3);
    v.x = *reinterpret_cast<uint32_t*>(&p0);
    v.y = *reinterpret_cast<uint32_t*>(&p1);
    *reinterpret_cast<uint2*>(g_Wh + (size_t)k * 4096 + ((size_t)(dir * 512 + d)) * 4) = v;
}

// ---------------------------------------------------------------------------
// fp16 GEMM: U(fp16) = A(fp16, MxK) * W(fp16, KxN)
// 128x128x32 tile, 256 threads (8 warps 2x4), warp tile 64x32, 3-stage cp.async,
// 2 CTAs/SM. R8/R11-measured best config; legacy HMMA pipe at ~90% ceiling.
// ---------------------------------------------------------------------------
#define BM 128
#define BN 128
#define BK 32
#define GSTAGES 3
#define A_ROWB 80                    // bytes per A smem row: (32+8) halves
#define B_ROWB 272                   // bytes per B smem row: (128+8) halves
#define A_SZ (128 * A_ROWB)          // 10240
#define B_SZ (BK * B_ROWB)           // 8704
#define STG_SZ (A_SZ + B_SZ)         // 18944
#define GEMM_SMEM (GSTAGES * STG_SZ) // 56832

__device__ __forceinline__ uint32_t smem_u32(const void* p) {
    uint32_t a;
    asm("{ .reg .u64 t; cvta.to.shared.u64 t, %1; cvt.u32.u64 %0, t; }" : "=r"(a) : "l"(p));
    return a;
}

__device__ __forceinline__ void mma16816(float c[4], const uint32_t a[4], const uint32_t b[2]) {
    asm volatile(
        "mma.sync.aligned.m16n8k16.row.col.f32.f16.f16.f32 "
        "{%0,%1,%2,%3}, {%4,%5,%6,%7}, {%8,%9}, {%0,%1,%2,%3};\n"
        : "+f"(c[0]), "+f"(c[1]), "+f"(c[2]), "+f"(c[3])
        : "r"(a[0]), "r"(a[1]), "r"(a[2]), "r"(a[3]), "r"(b[0]), "r"(b[1]));
}

template <int K>
__global__ __launch_bounds__(256, 2) void k_gemm() {
    extern __shared__ char smem[];
    const uint32_t sbase = smem_u32(smem);

    const int tid  = threadIdx.x;
    const int warp = tid >> 5;
    const int lane = tid & 31;
    const int wm = warp & 1;    // 0..1 -> 64-row slab
    const int wn = warp >> 1;   // 0..3 -> 32-col slab
    const size_t rowBase = (size_t)blockIdx.y * BM;
    const int    colBase = blockIdx.x * BN;
    const int    KT      = K / BK;

    const __half* Ag = g_Ah;
    const __half* Wg = g_Wh;

    float acc[4][4][4];
#pragma unroll
    for (int i = 0; i < 4; i++)
#pragma unroll
        for (int j = 0; j < 4; j++)
#pragma unroll
            for (int k = 0; k < 4; k++) acc[i][j][k] = 0.0f;

    auto loadStage = [&](int kt, int buf) {
        uint32_t sA = sbase + buf * STG_SZ;
        uint32_t sB = sA + A_SZ;
#pragma unroll
        for (int it = 0; it < 2; it++) {   // A: 512 x 16B chunks
            int cid = tid + it * 256;
            int r = cid >> 2, ch = cid & 3;
            const __half* g = Ag + (rowBase + r) * (size_t)K + kt * BK + ch * 8;
            uint32_t s = sA + (uint32_t)(r * A_ROWB + ch * 16);
            asm volatile("cp.async.cg.shared.global [%0], [%1], 16;\n" :: "r"(s), "l"(g));
        }
#pragma unroll
        for (int it = 0; it < 2; it++) {   // B: 512 x 16B chunks
            int cid = tid + it * 256;
            int r = cid >> 4, ch = cid & 15;
            const __half* g = Wg + (size_t)(kt * BK + r) * 4096 + colBase + ch * 8;
            uint32_t s = sB + (uint32_t)(r * B_ROWB + ch * 16);
            asm volatile("cp.async.cg.shared.global [%0], [%1], 16;\n" :: "r"(s), "l"(g));
        }
        asm volatile("cp.async.commit_group;\n" ::: "memory");
    };

    // Prologue: stages 0,1
    loadStage(0, 0);
    loadStage(1, 1);

    int buf = 0;
    for (int kt = 0; kt < KT; kt++) {
        if (kt + 1 < KT) asm volatile("cp.async.wait_group 1;\n" ::: "memory");
        else             asm volatile("cp.async.wait_group 0;\n" ::: "memory");
        __syncthreads();

        // Prefetch stage kt+2 into the buffer freed last iteration.
        if (kt + 2 < KT) loadStage(kt + 2, (buf + 2) % GSTAGES);

        const uint32_t sA = sbase + buf * STG_SZ;
        const uint32_t sB = sA + A_SZ;

#pragma unroll
        for (int kk = 0; kk < 2; kk++) {   // two k16 halves of BK=32
            uint32_t a[4][4];
#pragma unroll
            for (int mt = 0; mt < 4; mt++) {
                int row = wm * 64 + mt * 16 + (lane & 15);
                int col = kk * 16 + (lane >> 4) * 8;
                uint32_t s = sA + (uint32_t)(row * A_ROWB + col * 2);
                asm volatile("ldmatrix.sync.aligned.m8n8.x4.shared.b16 {%0,%1,%2,%3}, [%4];\n"
                             : "=r"(a[mt][0]), "=r"(a[mt][1]), "=r"(a[mt][2]), "=r"(a[mt][3])
                             : "r"(s));
            }
            uint32_t bf[4][2];
#pragma unroll
            for (int nh = 0; nh < 2; nh++) {
                int krow = kk * 16 + (lane & 15);
                int ncol = wn * 32 + nh * 16 + (lane >> 4) * 8;
                uint32_t s = sB + (uint32_t)(krow * B_ROWB + ncol * 2);
                uint32_t r0, r1, r2, r3;
                asm volatile("ldmatrix.sync.aligned.m8n8.x4.trans.shared.b16 {%0,%1,%2,%3}, [%4];\n"
                             : "=r"(r0), "=r"(r1), "=r"(r2), "=r"(r3)
                             : "r"(s));
                bf[nh * 2][0] = r0; bf[nh * 2][1] = r1;
                bf[nh * 2 + 1][0] = r2; bf[nh * 2 + 1][1] = r3;
            }
#pragma unroll
            for (int mt = 0; mt < 4; mt++)
#pragma unroll
                for (int nt = 0; nt < 4; nt++)
                    mma16816(acc[mt][nt], a[mt], bf[nt]);
        }
        buf = (buf + 1) % GSTAGES;
    }

    // Epilogue -> g_Uh fp16 (half2 stores)
#pragma unroll
    for (int mt = 0; mt < 4; mt++) {
#pragma unroll
        for (int nt = 0; nt < 4; nt++) {
            int r0 = wm * 64 + mt * 16 + (lane >> 2);
            int c0 = wn * 32 + nt * 8 + (lane & 3) * 2;
            __half* o1 = g_Uh + (rowBase + r0) * (size_t)4096 + colBase + c0;
            __half* o2 = g_Uh + (rowBase + r0 + 8) * (size_t)4096 + colBase + c0;
            *reinterpret_cast<__half2*>(o1) = __floats2half2_rn(acc[mt][nt][0], acc[mt][nt][1]);
            *reinterpret_cast<__half2*>(o2) = __floats2half2_rn(acc[mt][nt][2], acc[mt][nt][3]);
        }
    }
}

// ---------------------------------------------------------------------------
// SRU recurrence: TWO d-values per thread (16384 threads). uint4 loads give
// 512B contiguous per warp-LDG (vs 256B) and half2/float2 stores give
// 128B/256B per warp-STG (vs 64B/128B) — attacks the measured ~56% DRAM
// burst efficiency. Ring depth 8, unroll 8 (static indices -> registers).
// ---------------------------------------------------------------------------
__device__ __forceinline__ float sigf(float x) {
    float t;
    asm("tanh.approx.f32 %0, %1;" : "=f"(t) : "f"(x * 0.5f));
    return fmaf(t, 0.5f, 0.5f);
}

__device__ __forceinline__ void rec_load(const __half* p, long stride, int ch, uint4 (&u)[4]) {
    const __half* pn = p + (long)ch * 4 * stride;
#pragma unroll
    for (int j = 0; j < 4; j++)
        u[j] = *reinterpret_cast<const uint4*>(pn + (long)j * stride);
}

template <int LAYER>
__device__ __forceinline__ void rec_comp(uint4 (&u)[4], int ch, float& c0, float& c1,
                                         float2 vfd, float2 vrd, float2 bfd, float2 brd,
                                         __half* hA, float* hO, long hstride) {
#pragma unroll
    for (int j = 0; j < 4; j++) {
        // layout: [xt0, fp0, rp0, xp0, xt1, fp1, rp1, xp1]
        __half2 ha0 = *reinterpret_cast<__half2*>(&u[j].x);   // (xt0, fp0)
        __half2 ha1 = *reinterpret_cast<__half2*>(&u[j].y);   // (rp0, xp0)
        __half2 hb0 = *reinterpret_cast<__half2*>(&u[j].z);   // (xt1, fp1)
        __half2 hb1 = *reinterpret_cast<__half2*>(&u[j].w);   // (rp1, xp1)
        float2 a0 = __half22float2(ha0);
        float2 b0 = __half22float2(ha1);
        float2 a1 = __half22float2(hb0);
        float2 b1 = __half22float2(hb1);

        float f0  = sigf(fmaf(vfd.x, c0, a0.y + bfd.x));
        float cn0 = fmaf(f0, c0 - a0.x, a0.x);
        float r0  = sigf(fmaf(vrd.x, c0, b0.x + brd.x));
        float xs0 = b0.y * SCALE_F;
        float h0  = fmaf(r0, cn0 - xs0, xs0);
        c0 = cn0;

        float f1  = sigf(fmaf(vfd.y, c1, a1.y + bfd.y));
        float cn1 = fmaf(f1, c1 - a1.x, a1.x);
        float r1  = sigf(fmaf(vrd.y, c1, b1.x + brd.y));
        float xs1 = b1.y * SCALE_F;
        float h1  = fmaf(r1, cn1 - xs1, xs1);
        c1 = cn1;

        long off = (long)(ch * 4 + j) * hstride;
        if (LAYER == 0)
            *reinterpret_cast<__half2*>(hA + off) = __floats2half2_rn(h0, h1);
        else
            *reinterpret_cast<float2*>(hO + off) = make_float2(h0, h1);
    }
}

template <int LAYER>
__global__ __launch_bounds__(64) void k_rec(const float* __restrict__ vf,
                                            const float* __restrict__ vr,
                                            const float* __restrict__ bfp,
                                            const float* __restrict__ brp,
                                            float* __restrict__ out1,
                                            float* __restrict__ c1out) {
    const int d0  = (blockIdx.x * blockDim.x + threadIdx.x) * 2;  // 0,2,..,510
    const int b   = blockIdx.y;                                   // 0..31
    const int dir = blockIdx.z;                                   // 0 fwd, 1 bwd

    const float2 vfd = *reinterpret_cast<const float2*>(vf  + dir * 512 + d0);
    const float2 vrd = *reinterpret_cast<const float2*>(vr  + dir * 512 + d0);
    const float2 bfd = *reinterpret_cast<const float2*>(bfp + dir * 512 + d0);
    const float2 brd = *reinterpret_cast<const float2*>(brp + dir * 512 + d0);

    const long stride  = dir ? -4096 : 4096;   // halves per timestep
    const long hstride = dir ? -1024 : 1024;
    const int  t0      = dir ? 1023 : 0;

    const __half* p  = g_Uh + ((size_t)b * 1024 + t0) * 4096 + ((size_t)(dir * 512 + d0)) * 4;
    __half*       hA = g_Ah + ((size_t)b * 1024 + t0) * 1024 + dir * 512 + d0;
    float*        hO = (LAYER == 1)
                       ? out1 + ((size_t)b * 1024 + t0) * 1024 + dir * 512 + d0
                       : nullptr;

    float c0 = 0.0f, c1 = 0.0f;
    uint4 ubuf[8][4];
#pragma unroll
    for (int s = 0; s < 7; s++) rec_load(p, stride, s, ubuf[s]);
#pragma unroll 8
    for (int ch = 0; ch < 256; ch++) {
        if (ch + 7 < 256) rec_load(p, stride, ch + 7, ubuf[(ch + 7) & 7]);
        rec_comp<LAYER>(ubuf[ch & 7], ch, c0, c1, vfd, vrd, bfd, brd, hA, hO, hstride);
    }
    if (LAYER == 1)
        *reinterpret_cast<float2*>(c1out + b * 1024 + dir * 512 + d0) = make_float2(c0, c1);
}

// ---------------------------------------------------------------------------
// Launch: cvt(seqs) -> cvt(W0) -> GEMM0 -> rec0 -> cvt(W1) -> GEMM1 -> rec1
// Output: d_out = [ c1 (32*1024 fp32) | out1 (32*1024*1024 fp32) ]
// ---------------------------------------------------------------------------
extern "C" void kernel_launch(void* const* d_in, const int* in_sizes, int n_in,
                              void* d_out, int out_size) {
    const float* seqs = (const float*)d_in[0];
    const float* W0   = (const float*)d_in[1];
    const float* vf0  = (const float*)d_in[2];
    const float* vr0  = (const float*)d_in[3];
    const float* bf0  = (const float*)d_in[4];
    const float* br0  = (const float*)d_in[5];
    const float* W1   = (const float*)d_in[6];
    const float* vf1  = (const float*)d_in[7];
    const float* vr1  = (const float*)d_in[8];
    const float* bf1  = (const float*)d_in[9];
    const float* br1  = (const float*)d_in[10];

    float* out  = (float*)d_out;
    float* c1   = out;            // (32, 1024)
    float* out1 = out + 32768;    // (32, 1024, 1024)

    cudaFuncSetAttribute(k_gemm<512>,  cudaFuncAttributeMaxDynamicSharedMemorySize, GEMM_SMEM);
    cudaFuncSetAttribute(k_gemm<1024>, cudaFuncAttributeMaxDynamicSharedMemorySize, GEMM_SMEM);

    // Layer 0
    k_cvtA<<<16384, 256>>>((const float4*)seqs, 4194304);
    k_cvtWT<<<2048, 256>>>(W0, 512);
    k_gemm<512><<<dim3(32, 256), 256, GEMM_SMEM>>>();
    k_rec<0><<<dim3(4, 32, 2), 64>>>(vf0, vr0, bf0, br0, nullptr, nullptr);

    // Layer 1
    k_cvtWT<<<4096, 256>>>(W1, 1024);
    k_gemm<1024><<<dim3(32, 256), 256, GEMM_SMEM>>>();
    k_rec<1><<<dim3(4, 32, 2), 64>>>(vf1, vr1, bf1, br1, out1, c1);
}

// round 15
// speedup vs baseline: 1.0315x; 1.0315x over previous
#include <cuda_runtime.h>
#include <cuda_fp16.h>
#include <cstdint>

// Dims: B=32, L=1024, E=512, D=512. M = 32768 rows, N = 4096. K0=512, K1=1024.
#define SCALE_F 1.4142135623730951f

// ---------------------------------------------------------------------------
// Scratch (device globals)
// ---------------------------------------------------------------------------
__device__ __half g_Ah[33554432];   // fp16 A: layer0 seqs (32768x512), then h0 (32768x1024)
__device__ __half g_Wh[4194304];    // fp16 W [K, 4096], COLUMNS PERMUTED (gate-interleaved)
__device__ __half g_Uh[134217728];  // fp16 U (32768 x 4096), gate-interleaved columns

// ---------------------------------------------------------------------------
// Converters
// ---------------------------------------------------------------------------
__global__ void k_cvtA(const float4* __restrict__ s, int n4) {
    int i = blockIdx.x * blockDim.x + threadIdx.x;
    if (i < n4) {
        float4 v = s[i];
        __half2* dp = reinterpret_cast<__half2*>(g_Ah);
        dp[2 * i]     = __floats2half2_rn(v.x, v.y);
        dp[2 * i + 1] = __floats2half2_rn(v.z, v.w);
    }
}

// W [K,4096] fp32 -> g_Wh [K,4096] fp16, columns permuted so U's 4 gate values
// for (dir,d) are contiguous: new col (dir*512+d)*4+gate = old col dir*2048+gate*512+d.
__global__ void k_cvtWT(const float* __restrict__ W, int K) {
    int id = blockIdx.x * blockDim.x + threadIdx.x;   // K * 1024 ids
    int d   = id & 511;
    int dir = (id >> 9) & 1;
    int k   = id >> 10;
    if (k >= K) return;
    const float* src = W + (size_t)k * 4096 + dir * 2048 + d;
    float w0 = src[0], w1 = src[512], w2 = src[1024], w3 = src[1536];
    uint2 v;
    __half2 p0 = __floats2half2_rn(w0, w1);
    __half2 p1 = __floats2half2_rn(w2, w3);
    v.x = *reinterpret_cast<uint32_t*>(&p0);
    v.y = *reinterpret_cast<uint32_t*>(&p1);
    *reinterpret_cast<uint2*>(g_Wh + (size_t)k * 4096 + ((size_t)(dir * 512 + d)) * 4) = v;
}

// ---------------------------------------------------------------------------
// fp16 GEMM: U(fp16) = A(fp16, MxK) * W(fp16, KxN)
// 128x128 tile, BK=64 (halves sync/wait count vs BK=32), 3-stage cp.async,
// 256 threads (8 warps 2x4), warp tile 64x32, 2 CTAs/SM (107.5KB smem/CTA).
// Same k-accumulation order as BK=32 version -> bit-identical results.
// ---------------------------------------------------------------------------
#define BM 128
#define BN 128
#define BK 64
#define GSTAGES 3
#define A_ROWB 144                   // bytes per A smem row: (64+8) halves
#define B_ROWB 272                   // bytes per B smem row: (128+8) halves
#define A_SZ (128 * A_ROWB)          // 18432
#define B_SZ (BK * B_ROWB)           // 17408
#define STG_SZ (A_SZ + B_SZ)         // 35840
#define GEMM_SMEM (GSTAGES * STG_SZ) // 107520

__device__ __forceinline__ uint32_t smem_u32(const void* p) {
    uint32_t a;
    asm("{ .reg .u64 t; cvta.to.shared.u64 t, %1; cvt.u32.u64 %0, t; }" : "=r"(a) : "l"(p));
    return a;
}

__device__ __forceinline__ void mma16816(float c[4], const uint32_t a[4], const uint32_t b[2]) {
    asm volatile(
        "mma.sync.aligned.m16n8k16.row.col.f32.f16.f16.f32 "
        "{%0,%1,%2,%3}, {%4,%5,%6,%7}, {%8,%9}, {%0,%1,%2,%3};\n"
        : "+f"(c[0]), "+f"(c[1]), "+f"(c[2]), "+f"(c[3])
        : "r"(a[0]), "r"(a[1]), "r"(a[2]), "r"(a[3]), "r"(b[0]), "r"(b[1]));
}

template <int K>
__global__ __launch_bounds__(256, 2) void k_gemm() {
    extern __shared__ char smem[];
    const uint32_t sbase = smem_u32(smem);

    const int tid  = threadIdx.x;
    const int warp = tid >> 5;
    const int lane = tid & 31;
    const int wm = warp & 1;    // 0..1 -> 64-row slab
    const int wn = warp >> 1;   // 0..3 -> 32-col slab
    const size_t rowBase = (size_t)blockIdx.y * BM;
    const int    colBase = blockIdx.x * BN;
    const int    KT      = K / BK;

    const __half* Ag = g_Ah;
    const __half* Wg = g_Wh;

    float acc[4][4][4];
#pragma unroll
    for (int i = 0; i < 4; i++)
#pragma unroll
        for (int j = 0; j < 4; j++)
#pragma unroll
            for (int k = 0; k < 4; k++) acc[i][j][k] = 0.0f;

    auto loadStage = [&](int kt, int buf) {
        uint32_t sA = sbase + buf * STG_SZ;
        uint32_t sB = sA + A_SZ;
#pragma unroll
        for (int it = 0; it < 4; it++) {   // A: 1024 x 16B chunks (128 rows x 8)
            int cid = tid + it * 256;
            int r = cid >> 3, ch = cid & 7;
            const __half* g = Ag + (rowBase + r) * (size_t)K + kt * BK + ch * 8;
            uint32_t s = sA + (uint32_t)(r * A_ROWB + ch * 16);
            asm volatile("cp.async.cg.shared.global [%0], [%1], 16;\n" :: "r"(s), "l"(g));
        }
#pragma unroll
        for (int it = 0; it < 4; it++) {   // B: 1024 x 16B chunks (64 rows x 16)
            int cid = tid + it * 256;
            int r = cid >> 4, ch = cid & 15;
            const __half* g = Wg + (size_t)(kt * BK + r) * 4096 + colBase + ch * 8;
            uint32_t s = sB + (uint32_t)(r * B_ROWB + ch * 16);
            asm volatile("cp.async.cg.shared.global [%0], [%1], 16;\n" :: "r"(s), "l"(g));
        }
        asm volatile("cp.async.commit_group;\n" ::: "memory");
    };

    // Prologue: stages 0,1
    loadStage(0, 0);
    loadStage(1, 1);

    int buf = 0;
    for (int kt = 0; kt < KT; kt++) {
        if (kt + 1 < KT) asm volatile("cp.async.wait_group 1;\n" ::: "memory");
        else             asm volatile("cp.async.wait_group 0;\n" ::: "memory");
        __syncthreads();

        // Prefetch stage kt+2 into the buffer freed last iteration.
        if (kt + 2 < KT) loadStage(kt + 2, (buf + 2) % GSTAGES);

        const uint32_t sA = sbase + buf * STG_SZ;
        const uint32_t sB = sA + A_SZ;

#pragma unroll
        for (int kk = 0; kk < 4; kk++) {   // four k16 slices of BK=64
            uint32_t a[4][4];
#pragma unroll
            for (int mt = 0; mt < 4; mt++) {
                int row = wm * 64 + mt * 16 + (lane & 15);
                int col = kk * 16 + (lane >> 4) * 8;
                uint32_t s = sA + (uint32_t)(row * A_ROWB + col * 2);
                asm volatile("ldmatrix.sync.aligned.m8n8.x4.shared.b16 {%0,%1,%2,%3}, [%4];\n"
                             : "=r"(a[mt][0]), "=r"(a[mt][1]), "=r"(a[mt][2]), "=r"(a[mt][3])
                             : "r"(s));
            }
            uint32_t bf[4][2];
#pragma unroll
            for (int nh = 0; nh < 2; nh++) {
                int krow = kk * 16 + (lane & 15);
                int ncol = wn * 32 + nh * 16 + (lane >> 4) * 8;
                uint32_t s = sB + (uint32_t)(krow * B_ROWB + ncol * 2);
                uint32_t r0, r1, r2, r3;
                asm volatile("ldmatrix.sync.aligned.m8n8.x4.trans.shared.b16 {%0,%1,%2,%3}, [%4];\n"
                             : "=r"(r0), "=r"(r1), "=r"(r2), "=r"(r3)
                             : "r"(s));
                bf[nh * 2][0] = r0; bf[nh * 2][1] = r1;
                bf[nh * 2 + 1][0] = r2; bf[nh * 2 + 1][1] = r3;
            }
#pragma unroll
            for (int mt = 0; mt < 4; mt++)
#pragma unroll
                for (int nt = 0; nt < 4; nt++)
                    mma16816(acc[mt][nt], a[mt], bf[nt]);
        }
        buf = (buf + 1) % GSTAGES;
    }

    // Epilogue -> g_Uh fp16 (half2 stores)
#pragma unroll
    for (int mt = 0; mt < 4; mt++) {
#pragma unroll
        for (int nt = 0; nt < 4; nt++) {
            int r0 = wm * 64 + mt * 16 + (lane >> 2);
            int c0 = wn * 32 + nt * 8 + (lane & 3) * 2;
            __half* o1 = g_Uh + (rowBase + r0) * (size_t)4096 + colBase + c0;
            __half* o2 = g_Uh + (rowBase + r0 + 8) * (size_t)4096 + colBase + c0;
            *reinterpret_cast<__half2*>(o1) = __floats2half2_rn(acc[mt][nt][0], acc[mt][nt][1]);
            *reinterpret_cast<__half2*>(o2) = __floats2half2_rn(acc[mt][nt][2], acc[mt][nt][3]);
        }
    }
}

// ---------------------------------------------------------------------------
// SRU recurrence: EXACT R12 config (measured best: 72.2us rec0).
// One thread per (b,d,dir), 128-thr blocks, 256 CTAs. fp16 gate-interleaved U
// -> one 8B load per step. Ring depth 8, unroll 8. tanh-based sigmoid.
// ---------------------------------------------------------------------------
__device__ __forceinline__ float sigf(float x) {
    float t;
    asm("tanh.approx.f32 %0, %1;" : "=f"(t) : "f"(x * 0.5f));
    return fmaf(t, 0.5f, 0.5f);
}

__device__ __forceinline__ void rec_load(const __half* p, long stride, int ch, uint2 (&u)[4]) {
    const __half* pn = p + (long)ch * 4 * stride;
#pragma unroll
    for (int j = 0; j < 4; j++)
        u[j] = *reinterpret_cast<const uint2*>(pn + (long)j * stride);
}

template <int LAYER>
__device__ __forceinline__ void rec_comp(uint2 (&u)[4], int ch, float& c,
                                         float vfd, float vrd, float bfd, float brd,
                                         __half* hA, float* hO, long hstride) {
#pragma unroll
    for (int j = 0; j < 4; j++) {
        __half2 h0 = *reinterpret_cast<__half2*>(&u[j].x);   // (xt, fp)
        __half2 h1 = *reinterpret_cast<__half2*>(&u[j].y);   // (rp, xp)
        float2 a = __half22float2(h0);
        float2 b = __half22float2(h1);
        float f  = sigf(fmaf(vfd, c, a.y + bfd));
        float cn = fmaf(f, c - a.x, a.x);
        float r  = sigf(fmaf(vrd, c, b.x + brd));
        float xs = b.y * SCALE_F;
        float h  = fmaf(r, cn - xs, xs);
        c = cn;
        long off = (long)(ch * 4 + j) * hstride;
        if (LAYER == 0) hA[off] = __float2half_rn(h);
        else            hO[off] = h;
    }
}

template <int LAYER>
__global__ __launch_bounds__(128) void k_rec(const float* __restrict__ vf,
                                             const float* __restrict__ vr,
                                             const float* __restrict__ bfp,
                                             const float* __restrict__ brp,
                                             float* __restrict__ out1,
                                             float* __restrict__ c1out) {
    const int d   = blockIdx.x * blockDim.x + threadIdx.x;  // 0..511
    const int b   = blockIdx.y;                             // 0..31
    const int dir = blockIdx.z;                             // 0 fwd, 1 bwd

    const float vfd = vf[dir * 512 + d];
    const float vrd = vr[dir * 512 + d];
    const float bfd = bfp[dir * 512 + d];
    const float brd = brp[dir * 512 + d];

    const long stride  = dir ? -4096 : 4096;   // halves per timestep
    const long hstride = dir ? -1024 : 1024;
    const int  t0      = dir ? 1023 : 0;

    const __half* p  = g_Uh + ((size_t)b * 1024 + t0) * 4096 + ((size_t)(dir * 512 + d)) * 4;
    __half*       hA = g_Ah + ((size_t)b * 1024 + t0) * 1024 + dir * 512 + d;
    float*        hO = (LAYER == 1)
                       ? out1 + ((size_t)b * 1024 + t0) * 1024 + dir * 512 + d
                       : nullptr;

    float c = 0.0f;
    uint2 ubuf[8][4];
#pragma unroll
    for (int s = 0; s < 7; s++) rec_load(p, stride, s, ubuf[s]);
#pragma unroll 8
    for (int ch = 0; ch < 256; ch++) {
        if (ch + 7 < 256) rec_load(p, stride, ch + 7, ubuf[(ch + 7) & 7]);
        rec_comp<LAYER>(ubuf[ch & 7], ch, c, vfd, vrd, bfd, brd, hA, hO, hstride);
    }
    if (LAYER == 1) c1out[b * 1024 + dir * 512 + d] = c;
}

// ---------------------------------------------------------------------------
// Launch: cvt(seqs) -> cvt(W0) -> GEMM0 -> rec0 -> cvt(W1) -> GEMM1 -> rec1
// Output: d_out = [ c1 (32*1024 fp32) | out1 (32*1024*1024 fp32) ]
// ---------------------------------------------------------------------------
extern "C" void kernel_launch(void* const* d_in, const int* in_sizes, int n_in,
                              void* d_out, int out_size) {
    const float* seqs = (const float*)d_in[0];
    const float* W0   = (const float*)d_in[1];
    const float* vf0  = (const float*)d_in[2];
    const float* vr0  = (const float*)d_in[3];
    const float* bf0  = (const float*)d_in[4];
    const float* br0  = (const float*)d_in[5];
    const float* W1   = (const float*)d_in[6];
    const float* vf1  = (const float*)d_in[7];
    const float* vr1  = (const float*)d_in[8];
    const float* bf1  = (const float*)d_in[9];
    const float* br1  = (const float*)d_in[10];

    float* out  = (float*)d_out;
    float* c1   = out;            // (32, 1024)
    float* out1 = out + 32768;    // (32, 1024, 1024)

    cudaFuncSetAttribute(k_gemm<512>,  cudaFuncAttributeMaxDynamicSharedMemorySize, GEMM_SMEM);
    cudaFuncSetAttribute(k_gemm<1024>, cudaFuncAttributeMaxDynamicSharedMemorySize, GEMM_SMEM);

    // Layer 0
    k_cvtA<<<16384, 256>>>((const float4*)seqs, 4194304);
    k_cvtWT<<<2048, 256>>>(W0, 512);
    k_gemm<512><<<dim3(32, 256), 256, GEMM_SMEM>>>();
    k_rec<0><<<dim3(4, 32, 2), 128>>>(vf0, vr0, bf0, br0, nullptr, nullptr);

    // Layer 1
    k_cvtWT<<<4096, 256>>>(W1, 1024);
    k_gemm<1024><<<dim3(32, 256), 256, GEMM_SMEM>>>();
    k_rec<1><<<dim3(4, 32, 2), 128>>>(vf1, vr1, bf1, br1, out1, c1);
}

// round 17
// speedup vs baseline: 1.0576x; 1.0253x over previous
#include <cuda_runtime.h>
#include <cuda_fp16.h>
#include <cstdint>

// Dims: B=32, L=1024, E=512, D=512. M = 32768 rows, N = 4096. K0=512, K1=1024.
#define SCALE_F 1.4142135623730951f

// ---------------------------------------------------------------------------
// Scratch (device globals)
// ---------------------------------------------------------------------------
__device__ __half g_Ah[33554432];   // fp16 A: layer0 seqs (32768x512), then h0 (32768x1024)
__device__ __half g_Wh[4194304];    // fp16 W [K, 4096], COLUMNS PERMUTED (gate-interleaved)
__device__ __half g_Uh[134217728];  // fp16 U (32768 x 4096), gate-interleaved columns

// ---------------------------------------------------------------------------
// Converters
// ---------------------------------------------------------------------------
__global__ void k_cvtA(const float4* __restrict__ s, int n4) {
    int i = blockIdx.x * blockDim.x + threadIdx.x;
    if (i < n4) {
        float4 v = s[i];
        __half2* dp = reinterpret_cast<__half2*>(g_Ah);
        dp[2 * i]     = __floats2half2_rn(v.x, v.y);
        dp[2 * i + 1] = __floats2half2_rn(v.z, v.w);
    }
}

// W [K,4096] fp32 -> g_Wh [K,4096] fp16, columns permuted so U's 4 gate values
// for (dir,d) are contiguous: new col (dir*512+d)*4+gate = old col dir*2048+gate*512+d.
__global__ void k_cvtWT(const float* __restrict__ W, int K) {
    int id = blockIdx.x * blockDim.x + threadIdx.x;   // K * 1024 ids
    int d   = id & 511;
    int dir = (id >> 9) & 1;
    int k   = id >> 10;
    if (k >= K) return;
    const float* src = W + (size_t)k * 4096 + dir * 2048 + d;
    float w0 = src[0], w1 = src[512], w2 = src[1024], w3 = src[1536];
    uint2 v;
    __half2 p0 = __floats2half2_rn(w0, w1);
    __half2 p1 = __floats2half2_rn(w2, w3);
    v.x = *reinterpret_cast<uint32_t*>(&p0);
    v.y = *reinterpret_cast<uint32_t*>(&p1);
    *reinterpret_cast<uint2*>(g_Wh + (size_t)k * 4096 + ((size_t)(dir * 512 + d)) * 4) = v;
}

// ---------------------------------------------------------------------------
// fp16 GEMM: U(fp16) = A(fp16, MxK) * W(fp16, KxN)
// 128x128 tile, BK=64, 3-stage cp.async, 256 threads (8 warps 2x4),
// warp tile 64x32, 2 CTAs/SM. R15-measured best (~94% of HMMA pipe). CLOSED.
// ---------------------------------------------------------------------------
#define BM 128
#define BN 128
#define BK 64
#define GSTAGES 3
#define A_ROWB 144                   // bytes per A smem row: (64+8) halves
#define B_ROWB 272                   // bytes per B smem row: (128+8) halves
#define A_SZ (128 * A_ROWB)          // 18432
#define B_SZ (BK * B_ROWB)           // 17408
#define STG_SZ (A_SZ + B_SZ)         // 35840
#define GEMM_SMEM (GSTAGES * STG_SZ) // 107520

__device__ __forceinline__ uint32_t smem_u32(const void* p) {
    uint32_t a;
    asm("{ .reg .u64 t; cvta.to.shared.u64 t, %1; cvt.u32.u64 %0, t; }" : "=r"(a) : "l"(p));
    return a;
}

__device__ __forceinline__ void mma16816(float c[4], const uint32_t a[4], const uint32_t b[2]) {
    asm volatile(
        "mma.sync.aligned.m16n8k16.row.col.f32.f16.f16.f32 "
        "{%0,%1,%2,%3}, {%4,%5,%6,%7}, {%8,%9}, {%0,%1,%2,%3};\n"
        : "+f"(c[0]), "+f"(c[1]), "+f"(c[2]), "+f"(c[3])
        : "r"(a[0]), "r"(a[1]), "r"(a[2]), "r"(a[3]), "r"(b[0]), "r"(b[1]));
}

template <int K>
__global__ __launch_bounds__(256, 2) void k_gemm() {
    extern __shared__ char smem[];
    const uint32_t sbase = smem_u32(smem);

    const int tid  = threadIdx.x;
    const int warp = tid >> 5;
    const int lane = tid & 31;
    const int wm = warp & 1;    // 0..1 -> 64-row slab
    const int wn = warp >> 1;   // 0..3 -> 32-col slab
    const size_t rowBase = (size_t)blockIdx.y * BM;
    const int    colBase = blockIdx.x * BN;
    const int    KT      = K / BK;

    const __half* Ag = g_Ah;
    const __half* Wg = g_Wh;

    float acc[4][4][4];
#pragma unroll
    for (int i = 0; i < 4; i++)
#pragma unroll
        for (int j = 0; j < 4; j++)
#pragma unroll
            for (int k = 0; k < 4; k++) acc[i][j][k] = 0.0f;

    auto loadStage = [&](int kt, int buf) {
        uint32_t sA = sbase + buf * STG_SZ;
        uint32_t sB = sA + A_SZ;
#pragma unroll
        for (int it = 0; it < 4; it++) {   // A: 1024 x 16B chunks (128 rows x 8)
            int cid = tid + it * 256;
            int r = cid >> 3, ch = cid & 7;
            const __half* g = Ag + (rowBase + r) * (size_t)K + kt * BK + ch * 8;
            uint32_t s = sA + (uint32_t)(r * A_ROWB + ch * 16);
            asm volatile("cp.async.cg.shared.global [%0], [%1], 16;\n" :: "r"(s), "l"(g));
        }
#pragma unroll
        for (int it = 0; it < 4; it++) {   // B: 1024 x 16B chunks (64 rows x 16)
            int cid = tid + it * 256;
            int r = cid >> 4, ch = cid & 15;
            const __half* g = Wg + (size_t)(kt * BK + r) * 4096 + colBase + ch * 8;
            uint32_t s = sB + (uint32_t)(r * B_ROWB + ch * 16);
            asm volatile("cp.async.cg.shared.global [%0], [%1], 16;\n" :: "r"(s), "l"(g));
        }
        asm volatile("cp.async.commit_group;\n" ::: "memory");
    };

    // Prologue: stages 0,1
    loadStage(0, 0);
    loadStage(1, 1);

    int buf = 0;
    for (int kt = 0; kt < KT; kt++) {
        if (kt + 1 < KT) asm volatile("cp.async.wait_group 1;\n" ::: "memory");
        else             asm volatile("cp.async.wait_group 0;\n" ::: "memory");
        __syncthreads();

        // Prefetch stage kt+2 into the buffer freed last iteration.
        if (kt + 2 < KT) loadStage(kt + 2, (buf + 2) % GSTAGES);

        const uint32_t sA = sbase + buf * STG_SZ;
        const uint32_t sB = sA + A_SZ;

#pragma unroll
        for (int kk = 0; kk < 4; kk++) {   // four k16 slices of BK=64
            uint32_t a[4][4];
#pragma unroll
            for (int mt = 0; mt < 4; mt++) {
                int row = wm * 64 + mt * 16 + (lane & 15);
                int col = kk * 16 + (lane >> 4) * 8;
                uint32_t s = sA + (uint32_t)(row * A_ROWB + col * 2);
                asm volatile("ldmatrix.sync.aligned.m8n8.x4.shared.b16 {%0,%1,%2,%3}, [%4];\n"
                             : "=r"(a[mt][0]), "=r"(a[mt][1]), "=r"(a[mt][2]), "=r"(a[mt][3])
                             : "r"(s));
            }
            uint32_t bf[4][2];
#pragma unroll
            for (int nh = 0; nh < 2; nh++) {
                int krow = kk * 16 + (lane & 15);
                int ncol = wn * 32 + nh * 16 + (lane >> 4) * 8;
                uint32_t s = sB + (uint32_t)(krow * B_ROWB + ncol * 2);
                uint32_t r0, r1, r2, r3;
                asm volatile("ldmatrix.sync.aligned.m8n8.x4.trans.shared.b16 {%0,%1,%2,%3}, [%4];\n"
                             : "=r"(r0), "=r"(r1), "=r"(r2), "=r"(r3)
                             : "r"(s));
                bf[nh * 2][0] = r0; bf[nh * 2][1] = r1;
                bf[nh * 2 + 1][0] = r2; bf[nh * 2 + 1][1] = r3;
            }
#pragma unroll
            for (int mt = 0; mt < 4; mt++)
#pragma unroll
                for (int nt = 0; nt < 4; nt++)
                    mma16816(acc[mt][nt], a[mt], bf[nt]);
        }
        buf = (buf + 1) % GSTAGES;
    }

    // Epilogue -> g_Uh fp16 (half2 stores)
#pragma unroll
    for (int mt = 0; mt < 4; mt++) {
#pragma unroll
        for (int nt = 0; nt < 4; nt++) {
            int r0 = wm * 64 + mt * 16 + (lane >> 2);
            int c0 = wn * 32 + nt * 8 + (lane & 3) * 2;
            __half* o1 = g_Uh + (rowBase + r0) * (size_t)4096 + colBase + c0;
            __half* o2 = g_Uh + (rowBase + r0 + 8) * (size_t)4096 + colBase + c0;
            *reinterpret_cast<__half2*>(o1) = __floats2half2_rn(acc[mt][nt][0], acc[mt][nt][1]);
            *reinterpret_cast<__half2*>(o2) = __floats2half2_rn(acc[mt][nt][2], acc[mt][nt][3]);
        }
    }
}

// ---------------------------------------------------------------------------
// SRU recurrence: one thread per (b,d,dir), 128-thr blocks, 256 CTAs.
// fp16 gate-interleaved U -> one 8B load per step.
// Ring depth 16, unroll 16 (16 | 256 -> all indices compile-time static).
// __ldcs on U (write-once/read-once: don't pollute L2), __stcs on out1.
// ---------------------------------------------------------------------------
__device__ __forceinline__ float sigf(float x) {
    float t;
    asm("tanh.approx.f32 %0, %1;" : "=f"(t) : "f"(x * 0.5f));
    return fmaf(t, 0.5f, 0.5f);
}

__device__ __forceinline__ void rec_load(const __half* p, long stride, int ch, uint2 (&u)[4]) {
    const __half* pn = p + (long)ch * 4 * stride;
#pragma unroll
    for (int j = 0; j < 4; j++)
        u[j] = __ldcs(reinterpret_cast<const uint2*>(pn + (long)j * stride));
}

template <int LAYER>
__device__ __forceinline__ void rec_comp(uint2 (&u)[4], int ch, float& c,
                                         float vfd, float vrd, float bfd, float brd,
                                         __half* hA, float* hO, long hstride) {
#pragma unroll
    for (int j = 0; j < 4; j++) {
        __half2 h0 = *reinterpret_cast<__half2*>(&u[j].x);   // (xt, fp)
        __half2 h1 = *reinterpret_cast<__half2*>(&u[j].y);   // (rp, xp)
        float2 a = __half22float2(h0);
        float2 b = __half22float2(h1);
        float f  = sigf(fmaf(vfd, c, a.y + bfd));
        float cn = fmaf(f, c - a.x, a.x);
        float r  = sigf(fmaf(vrd, c, b.x + brd));
        float xs = b.y * SCALE_F;
        float h  = fmaf(r, cn - xs, xs);
        c = cn;
        long off = (long)(ch * 4 + j) * hstride;
        if (LAYER == 0) hA[off] = __float2half_rn(h);
        else            __stcs(hO + off, h);
    }
}

template <int LAYER>
__global__ __launch_bounds__(128) void k_rec(const float* __restrict__ vf,
                                             const float* __restrict__ vr,
                                             const float* __restrict__ bfp,
                                             const float* __restrict__ brp,
                                             float* __restrict__ out1,
                                             float* __restrict__ c1out) {
    const int d   = blockIdx.x * blockDim.x + threadIdx.x;  // 0..511
    const int b   = blockIdx.y;                             // 0..31
    const int dir = blockIdx.z;                             // 0 fwd, 1 bwd

    const float vfd = vf[dir * 512 + d];
    const float vrd = vr[dir * 512 + d];
    const float bfd = bfp[dir * 512 + d];
    const float brd = brp[dir * 512 + d];

    const long stride  = dir ? -4096 : 4096;   // halves per timestep
    const long hstride = dir ? -1024 : 1024;
    const int  t0      = dir ? 1023 : 0;

    const __half* p  = g_Uh + ((size_t)b * 1024 + t0) * 4096 + ((size_t)(dir * 512 + d)) * 4;
    __half*       hA = g_Ah + ((size_t)b * 1024 + t0) * 1024 + dir * 512 + d;
    float*        hO = (LAYER == 1)
                       ? out1 + ((size_t)b * 1024 + t0) * 1024 + dir * 512 + d
                       : nullptr;

    float c = 0.0f;
    uint2 ubuf[16][4];
#pragma unroll
    for (int s = 0; s < 15; s++) rec_load(p, stride, s, ubuf[s]);
#pragma unroll 16
    for (int ch = 0; ch < 256; ch++) {
        if (ch + 15 < 256) rec_load(p, stride, ch + 15, ubuf[(ch + 15) & 15]);
        rec_comp<LAYER>(ubuf[ch & 15], ch, c, vfd, vrd, bfd, brd, hA, hO, hstride);
    }
    if (LAYER == 1) c1out[b * 1024 + dir * 512 + d] = c;
}

// ---------------------------------------------------------------------------
// Launch: cvt(seqs) -> cvt(W0) -> GEMM0 -> rec0 -> cvt(W1) -> GEMM1 -> rec1
// Output: d_out = [ c1 (32*1024 fp32) | out1 (32*1024*1024 fp32) ]
// ---------------------------------------------------------------------------
extern "C" void kernel_launch(void* const* d_in, const int* in_sizes, int n_in,
                              void* d_out, int out_size) {
    const float* seqs = (const float*)d_in[0];
    const float* W0   = (const float*)d_in[1];
    const float* vf0  = (const float*)d_in[2];
    const float* vr0  = (const float*)d_in[3];
    const float* bf0  = (const float*)d_in[4];
    const float* br0  = (const float*)d_in[5];
    const float* W1   = (const float*)d_in[6];
    const float* vf1  = (const float*)d_in[7];
    const float* vr1  = (const float*)d_in[8];
    const float* bf1  = (const float*)d_in[9];
    const float* br1  = (const float*)d_in[10];

    float* out  = (float*)d_out;
    float* c1   = out;            // (32, 1024)
    float* out1 = out + 32768;    // (32, 1024, 1024)

    cudaFuncSetAttribute(k_gemm<512>,  cudaFuncAttributeMaxDynamicSharedMemorySize, GEMM_SMEM);
    cudaFuncSetAttribute(k_gemm<1024>, cudaFuncAttributeMaxDynamicSharedMemorySize, GEMM_SMEM);

    // Layer 0
    k_cvtA<<<16384, 256>>>((const float4*)seqs, 4194304);
    k_cvtWT<<<2048, 256>>>(W0, 512);
    k_gemm<512><<<dim3(32, 256), 256, GEMM_SMEM>>>();
    k_rec<0><<<dim3(4, 32, 2), 128>>>(vf0, vr0, bf0, br0, nullptr, nullptr);

    // Layer 1
    k_cvtWT<<<4096, 256>>>(W1, 1024);
    k_gemm<1024><<<dim3(32, 256), 256, GEMM_SMEM>>>();
    k_rec<1><<<dim3(4, 32, 2), 128>>>(vf1, vr1, bf1, br1, out1, c1);
}